// round 8
// baseline (speedup 1.0000x reference)
#include <cuda_runtime.h>
#include <math.h>

#define B_  8
#define T_  256
#define U_  64
#define U1_ 65
#define V_  512
#define S_  66                         // padded SMEM row stride (2-way conflict max)
#define SENT -1e30f

#define ROWS (B_ * T_ * U1_)           // 133120

__device__ float g_blank[ROWS];
__device__ float g_emit[ROWS];
__device__ float g_partial[B_];

// ---------------------------------------------------------------------------
// Kernel 1: per-row log-softmax; extract blank (v=0) and emit (v=target).
// One warp per (b,t,u) row; single pass, registers only. ~80% DRAM (roofline).
// ---------------------------------------------------------------------------
__global__ void __launch_bounds__(256) lse_kernel(const float* __restrict__ pred,
                                                  const int* __restrict__ target) {
    const int row  = blockIdx.x * 8 + (threadIdx.x >> 5);
    const int lane = threadIdx.x & 31;
    if (row >= ROWS) return;

    const float4* p = (const float4*)(pred + (size_t)row * V_);
    float4 r[4];
#pragma unroll
    for (int k = 0; k < 4; k++) r[k] = p[k * 32 + lane];

    float m = fmaxf(fmaxf(r[0].x, r[0].y), fmaxf(r[0].z, r[0].w));
#pragma unroll
    for (int k = 1; k < 4; k++)
        m = fmaxf(m, fmaxf(fmaxf(r[k].x, r[k].y), fmaxf(r[k].z, r[k].w)));
#pragma unroll
    for (int o = 16; o > 0; o >>= 1)
        m = fmaxf(m, __shfl_xor_sync(0xffffffffu, m, o));

    float s = 0.f;
#pragma unroll
    for (int k = 0; k < 4; k++)
        s += __expf(r[k].x - m) + __expf(r[k].y - m) +
             __expf(r[k].z - m) + __expf(r[k].w - m);
#pragma unroll
    for (int o = 16; o > 0; o >>= 1)
        s += __shfl_xor_sync(0xffffffffu, s, o);

    const float lse = m + __logf(s);

    const int u = row % U1_;
    const int b = row / (T_ * U1_);

    if (lane == 0) g_blank[row] = r[0].x - lse;

    if (u < U_) {
        const int tgt = target[b * U_ + u];
        float e = 0.f;
        bool have = false;
#pragma unroll
        for (int k = 0; k < 4; k++) {
            const int base = (k * 32 + lane) << 2;
            if (tgt >= base && tgt < base + 4) {
                have = true;
                if (tgt == base)     e = r[k].x;
                if (tgt == base + 1) e = r[k].y;
                if (tgt == base + 2) e = r[k].z;
                if (tgt == base + 3) e = r[k].w;
            }
        }
        if (have) g_emit[row] = e - lse;
    }
}

// ---------------------------------------------------------------------------
// Kernel 2: single-warp wavefront DP, ZERO branches in the 320-step loop.
//   sb[r][u] = blank(r-1, u); row 0 = SENT  (t==0 boundary -> q wins exactly)
//   se[t][c] = emit(t, c-1);  col 0 = SENT  (u==0 boundary -> p wins exactly)
// Lane l owns u = {2l, 2l+1}; lane 31 also owns u = 64.
// lae(SENT+x, q) == q exactly: exp underflows to 0, logf(1) == 0.
// ---------------------------------------------------------------------------
__device__ __forceinline__ float lae(float a, float b) {
    const float mx = fmaxf(a, b);
    return mx + __logf(1.f + __expf(-fabsf(a - b)));
}

__global__ void __launch_bounds__(128) dp_kernel(const int* __restrict__ pred_len,
                                                 const int* __restrict__ target_len) {
    const int b = blockIdx.x;
    extern __shared__ float sm[];
    float* sb = sm;                      // (T_+1) x S_
    float* se = sm + (T_ + 1) * S_;      // T_ x S_

    const float* gb = g_blank + b * T_ * U1_;
    const float* ge = g_emit  + b * T_ * U1_;
    const int wid  = threadIdx.x >> 5;
    const int lane = threadIdx.x & 31;

    for (int u = threadIdx.x; u < S_; u += 128) sb[u] = SENT;       // sentinel row
    for (int t = wid; t < T_; t += 4) {
        for (int u = lane; u < U1_; u += 32)
            sb[(t + 1) * S_ + u] = gb[t * U1_ + u];
        if (lane == 0) se[t * S_] = SENT;                           // sentinel col
        for (int u = lane; u < U_; u += 32)
            se[t * S_ + u + 1] = ge[t * U1_ + u];
    }
    __syncthreads();
    if (threadIdx.x >= 32) return;

    const int l  = lane;
    const int u0 = 2 * l;
    const int u1 = 2 * l + 1;

    const int plast = pred_len[b] - 1;
    const int tlen  = target_len[b];
    const float fblank = sb[(plast + 1) * S_ + tlen];               // blank(plast,tlen)

    const int nh0 = plast + u0;          // diagonal where (plast, u0) is computed
    const int nh1 = plast + u1;
    const int nh2 = plast + 64;

    float a0 = 0.f, a1 = 0.f, a2 = 0.f;  // a0 of lane 0 == alpha(0,0) = 0 (the seed)
    float res0 = 0.f, res1 = 0.f, res2 = 0.f;

#pragma unroll 2
    for (int n = 1; n < T_ + U_; n++) {
        const int t0 = n - u0;
        const int t1 = t0 - 1;
        const int t2 = n - 64;

        const int c0 = max(t0, 0), c1 = max(t1, 0), c2 = max(t2, 0);
        const float bl0 = sb[min(c0, T_) * S_ + u0];
        const float bl1 = sb[min(c1, T_) * S_ + u1];
        const float bl2 = sb[min(c2, T_) * S_ + 64];
        const float em0 = se[min(c0, T_ - 1) * S_ + u0];
        const float em1 = se[min(c1, T_ - 1) * S_ + u1];
        const float em2 = se[min(c2, T_ - 1) * S_ + 64];

        const float left0 = __shfl_up_sync(0xffffffffu, a1, 1);     // alpha[t0][u0-1]

        const float v0 = lae(a0 + bl0, left0 + em0);
        const float v1 = lae(a1 + bl1, a0 + em1);                   // old a0
        const float v2 = lae(a2 + bl2, a1 + em2);                   // old a1

        res0 = (n == nh0) ? v0 : res0;
        res1 = (n == nh1) ? v1 : res1;
        res2 = (n == nh2) ? v2 : res2;

        a0 = ((unsigned)t0 < (unsigned)T_) ? v0 : a0;
        a1 = ((unsigned)t1 < (unsigned)T_) ? v1 : a1;
        a2 = ((unsigned)t2 < (unsigned)T_) ? v2 : a2;
    }

    if (u0 == tlen)            g_partial[b] = -(res0 + fblank);
    if (u1 == tlen)            g_partial[b] = -(res1 + fblank);
    if (l == 31 && tlen == 64) g_partial[b] = -(res2 + fblank);
}

// ---------------------------------------------------------------------------
// Kernel 3: mean over batch -> d_out[0]
// ---------------------------------------------------------------------------
__global__ void finish_kernel(float* __restrict__ out) {
    if (threadIdx.x == 0) {
        float s = 0.f;
#pragma unroll
        for (int i = 0; i < B_; i++) s += g_partial[i];
        out[0] = s * (1.f / B_);
    }
}

extern "C" void kernel_launch(void* const* d_in, const int* in_sizes, int n_in,
                              void* d_out, int out_size) {
    const float* pred       = (const float*)d_in[0];
    const int*   target     = (const int*)d_in[1];
    const int*   pred_len   = (const int*)d_in[2];
    const int*   target_len = (const int*)d_in[3];
    float*       out        = (float*)d_out;

    const int smem_bytes = (2 * T_ + 1) * S_ * (int)sizeof(float);

    static bool attr_done = false;
    if (!attr_done) {
        cudaFuncSetAttribute(dp_kernel, cudaFuncAttributeMaxDynamicSharedMemorySize, smem_bytes);
        attr_done = true;
    }

    lse_kernel<<<ROWS / 8, 256>>>(pred, target);
    dp_kernel<<<B_, 128, smem_bytes>>>(pred_len, target_len);
    finish_kernel<<<1, 32>>>(out);
}

// round 9
// speedup vs baseline: 1.0025x; 1.0025x over previous
#include <cuda_runtime.h>
#include <math.h>

#define B_  8
#define T_  256
#define U_  64
#define U1_ 65
#define V_  512
#define S_  66
#define SENT -1e30f
#define LOG2E 1.4426950408889634f
#define LN2   0.6931471805599453f

#define ROWS (B_ * T_ * U1_)

__device__ float g_blank[ROWS];   // base-2 log-probs
__device__ float g_emit[ROWS];    // base-2 log-probs
__device__ float g_partial[B_];   // base-2 negative losses

__device__ __forceinline__ float ex2(float x) {
    float y; asm("ex2.approx.f32 %0, %1;" : "=f"(y) : "f"(x)); return y;
}
__device__ __forceinline__ float lg2(float x) {
    float y; asm("lg2.approx.f32 %0, %1;" : "=f"(y) : "f"(x)); return y;
}
// log2-add-exp2: all operands in base-2 log units
__device__ __forceinline__ float lae2(float a, float b) {
    const float mx = fmaxf(a, b);
    return mx + lg2(1.f + ex2(-fabsf(a - b)));
}

// ---------------------------------------------------------------------------
// Kernel 1: per-row log-softmax (HBM roofline). Outputs scaled by log2e.
// ---------------------------------------------------------------------------
__global__ void __launch_bounds__(256) lse_kernel(const float* __restrict__ pred,
                                                  const int* __restrict__ target) {
    const int row  = blockIdx.x * 8 + (threadIdx.x >> 5);
    const int lane = threadIdx.x & 31;
    if (row >= ROWS) return;

    const float4* p = (const float4*)(pred + (size_t)row * V_);
    float4 r[4];
#pragma unroll
    for (int k = 0; k < 4; k++) r[k] = p[k * 32 + lane];

    float m = fmaxf(fmaxf(r[0].x, r[0].y), fmaxf(r[0].z, r[0].w));
#pragma unroll
    for (int k = 1; k < 4; k++)
        m = fmaxf(m, fmaxf(fmaxf(r[k].x, r[k].y), fmaxf(r[k].z, r[k].w)));
#pragma unroll
    for (int o = 16; o > 0; o >>= 1)
        m = fmaxf(m, __shfl_xor_sync(0xffffffffu, m, o));

    float s = 0.f;
#pragma unroll
    for (int k = 0; k < 4; k++)
        s += __expf(r[k].x - m) + __expf(r[k].y - m) +
             __expf(r[k].z - m) + __expf(r[k].w - m);
#pragma unroll
    for (int o = 16; o > 0; o >>= 1)
        s += __shfl_xor_sync(0xffffffffu, s, o);

    const float lse = m + __logf(s);

    const int u = row % U1_;
    const int b = row / (T_ * U1_);

    if (lane == 0) g_blank[row] = (r[0].x - lse) * LOG2E;

    if (u < U_) {
        const int tgt = target[b * U_ + u];
        float e = 0.f;
        bool have = false;
#pragma unroll
        for (int k = 0; k < 4; k++) {
            const int base = (k * 32 + lane) << 2;
            if (tgt >= base && tgt < base + 4) {
                have = true;
                if (tgt == base)     e = r[k].x;
                if (tgt == base + 1) e = r[k].y;
                if (tgt == base + 2) e = r[k].z;
                if (tgt == base + 3) e = r[k].w;
            }
        }
        if (have) g_emit[row] = (e - lse) * LOG2E;
    }
}

// ---------------------------------------------------------------------------
// Kernel 2: single-warp wavefront DP, manually software-pipelined.
//   sb[r][u] = blank(r-1,u), row 0 = SENT;  se[t][c] = emit(t,c-1), col 0 = SENT.
// Lane l owns u={2l,2l+1}; lane 31 also u=64. Loads for step n+1 issue before
// step n's math; the cross-lane shfl for step n+1 issues at the end of step n.
// ---------------------------------------------------------------------------
__global__ void __launch_bounds__(128) dp_kernel(const int* __restrict__ pred_len,
                                                 const int* __restrict__ target_len) {
    const int b = blockIdx.x;
    extern __shared__ float sm[];
    float* sb = sm;                      // (T_+1) x S_
    float* se = sm + (T_ + 1) * S_;      // T_ x S_

    const float* gb = g_blank + b * T_ * U1_;
    const float* ge = g_emit  + b * T_ * U1_;
    const int wid  = threadIdx.x >> 5;
    const int lane = threadIdx.x & 31;

    for (int u = threadIdx.x; u < S_; u += 128) sb[u] = SENT;
    for (int t = wid; t < T_; t += 4) {
        for (int u = lane; u < U1_; u += 32)
            sb[(t + 1) * S_ + u] = gb[t * U1_ + u];
        if (lane == 0) se[t * S_] = SENT;
        for (int u = lane; u < U_; u += 32)
            se[t * S_ + u + 1] = ge[t * U1_ + u];
    }
    __syncthreads();
    if (threadIdx.x >= 32) return;

    const int l  = lane;
    const int u0 = 2 * l;
    const int u1 = 2 * l + 1;

    const int plast = pred_len[b] - 1;
    const int tlen  = target_len[b];
    const float fblank = sb[(plast + 1) * S_ + tlen];

    const int nh0 = plast + u0;
    const int nh1 = plast + u1;
    const int nh2 = plast + 64;

#define ADDRS(N, A0, A1, A2, E0, E1, E2)                         \
    {   const int t0_ = (N) - u0;                                 \
        const int c0_ = max(t0_, 0), c1_ = max(t0_ - 1, 0),       \
                  c2_ = max((N) - 64, 0);                         \
        A0 = min(c0_, T_) * S_ + u0;                              \
        A1 = min(c1_, T_) * S_ + u1;                              \
        A2 = min(c2_, T_) * S_ + 64;                              \
        E0 = min(c0_, T_ - 1) * S_ + u0;                          \
        E1 = min(c1_, T_ - 1) * S_ + u1;                          \
        E2 = min(c2_, T_ - 1) * S_ + 64; }

    // prologue: loads for n = 1
    int A0, A1, A2, E0, E1, E2;
    ADDRS(1, A0, A1, A2, E0, E1, E2);
    float bl0c = sb[A0], bl1c = sb[A1], bl2c = sb[A2];
    float em0c = se[E0], em1c = se[E1], em2c = se[E2];

    float a0 = 0.f, a1 = 0.f, a2 = 0.f;
    float res0 = 0.f, res1 = 0.f, res2 = 0.f;
    float left0 = 0.f;                    // dead for n=1 (em sentinel kills it)

#pragma unroll 4
    for (int n = 1; n < T_ + U_; n++) {
        // issue loads for step n+1 first (addresses independent of alpha chain;
        // n+1 == 320 clamps safely inside the tables)
        ADDRS(n + 1, A0, A1, A2, E0, E1, E2);
        const float bl0n = sb[A0], bl1n = sb[A1], bl2n = sb[A2];
        const float em0n = se[E0], em1n = se[E1], em2n = se[E2];

        // compute step n with pre-loaded values
        const float v0 = lae2(a0 + bl0c, left0 + em0c);
        const float v1 = lae2(a1 + bl1c, a0 + em1c);
        const float v2 = lae2(a2 + bl2c, a1 + em2c);

        res0 = (n == nh0) ? v0 : res0;
        res1 = (n == nh1) ? v1 : res1;
        res2 = (n == nh2) ? v2 : res2;

        const int t0 = n - u0;
        a0 = ((unsigned)t0       < (unsigned)T_) ? v0 : a0;
        a1 = ((unsigned)(t0 - 1) < (unsigned)T_) ? v1 : a1;
        a2 = ((unsigned)(n - 64) < (unsigned)T_) ? v2 : a2;

        // cross-lane value for step n+1: alpha[.][u0-1] = neighbor's a1
        left0 = __shfl_up_sync(0xffffffffu, a1, 1);

        bl0c = bl0n; bl1c = bl1n; bl2c = bl2n;
        em0c = em0n; em1c = em1n; em2c = em2n;
    }
#undef ADDRS

    if (u0 == tlen)            g_partial[b] = -(res0 + fblank);
    if (u1 == tlen)            g_partial[b] = -(res1 + fblank);
    if (l == 31 && tlen == 64) g_partial[b] = -(res2 + fblank);
}

// ---------------------------------------------------------------------------
// Kernel 3: mean over batch (convert base-2 -> nat) -> d_out[0]
// ---------------------------------------------------------------------------
__global__ void finish_kernel(float* __restrict__ out) {
    if (threadIdx.x == 0) {
        float s = 0.f;
#pragma unroll
        for (int i = 0; i < B_; i++) s += g_partial[i];
        out[0] = s * (LN2 / B_);
    }
}

extern "C" void kernel_launch(void* const* d_in, const int* in_sizes, int n_in,
                              void* d_out, int out_size) {
    const float* pred       = (const float*)d_in[0];
    const int*   target     = (const int*)d_in[1];
    const int*   pred_len   = (const int*)d_in[2];
    const int*   target_len = (const int*)d_in[3];
    float*       out        = (float*)d_out;

    const int smem_bytes = ((T_ + 1) + T_) * S_ * (int)sizeof(float);

    static bool attr_done = false;
    if (!attr_done) {
        cudaFuncSetAttribute(dp_kernel, cudaFuncAttributeMaxDynamicSharedMemorySize, smem_bytes);
        attr_done = true;
    }

    lse_kernel<<<ROWS / 8, 256>>>(pred, target);
    dp_kernel<<<B_, 128, smem_bytes>>>(pred_len, target_len);
    finish_kernel<<<1, 32>>>(out);
}

// round 10
// speedup vs baseline: 1.6572x; 1.6531x over previous
#include <cuda_runtime.h>
#include <math.h>

#define B_  8
#define T_  256
#define U_  64
#define U1_ 65
#define V_  512
#define D_  320                        // number of anti-diagonals t+u
#define W_  66                         // padded diagonal row width (33 float2)
#define SENT  -1e30f
#define LOG2E 1.4426950408889634f
#define LN2   0.6931471805599453f

#define ROWS (B_ * T_ * U1_)
#define DIAG_ELEMS (B_ * D_ * W_)      // 168960

// Diagonal-major tables (base-2 log units), pre-filled with SENT:
//   g_dB[b][d][u]   = blank(t,u)*log2e  at d = t+u   (invalid slots = SENT)
//   g_dE[b][d][u+1] = emit (t,u)*log2e  at d = t+u   (col 0 & invalid = SENT)
__device__ float g_dB[DIAG_ELEMS];
__device__ float g_dE[DIAG_ELEMS];
__device__ float g_partial[B_];

__device__ __forceinline__ float ex2(float x) {
    float y; asm("ex2.approx.f32 %0, %1;" : "=f"(y) : "f"(x)); return y;
}
__device__ __forceinline__ float lg2(float x) {
    float y; asm("lg2.approx.f32 %0, %1;" : "=f"(y) : "f"(x)); return y;
}
__device__ __forceinline__ float lae2(float a, float b) {
    const float mx = fmaxf(a, b);
    return mx + lg2(1.f + ex2(-fabsf(a - b)));
}

// ---------------------------------------------------------------------------
// Kernel 0: sentinel fill of both diagonal tables.
// ---------------------------------------------------------------------------
__global__ void fill_kernel() {
    const int i = blockIdx.x * 1024 + threadIdx.x;
    if (i < DIAG_ELEMS) { g_dB[i] = SENT; g_dE[i] = SENT; }
}

// ---------------------------------------------------------------------------
// Kernel 1: per-row log-softmax (HBM roofline); writes diagonal-major tables.
// ---------------------------------------------------------------------------
__global__ void __launch_bounds__(256) lse_kernel(const float* __restrict__ pred,
                                                  const int* __restrict__ target) {
    const int row  = blockIdx.x * 8 + (threadIdx.x >> 5);
    const int lane = threadIdx.x & 31;
    if (row >= ROWS) return;

    const float4* p = (const float4*)(pred + (size_t)row * V_);
    float4 r[4];
#pragma unroll
    for (int k = 0; k < 4; k++) r[k] = p[k * 32 + lane];

    float m = fmaxf(fmaxf(r[0].x, r[0].y), fmaxf(r[0].z, r[0].w));
#pragma unroll
    for (int k = 1; k < 4; k++)
        m = fmaxf(m, fmaxf(fmaxf(r[k].x, r[k].y), fmaxf(r[k].z, r[k].w)));
#pragma unroll
    for (int o = 16; o > 0; o >>= 1)
        m = fmaxf(m, __shfl_xor_sync(0xffffffffu, m, o));

    float s = 0.f;
#pragma unroll
    for (int k = 0; k < 4; k++)
        s += __expf(r[k].x - m) + __expf(r[k].y - m) +
             __expf(r[k].z - m) + __expf(r[k].w - m);
#pragma unroll
    for (int o = 16; o > 0; o >>= 1)
        s += __shfl_xor_sync(0xffffffffu, s, o);

    const float lse = m + __logf(s);

    const int u  = row % U1_;
    const int bt = row / U1_;
    const int t  = bt % T_;
    const int b  = bt / T_;
    const int d  = t + u;

    if (lane == 0)
        g_dB[(b * D_ + d) * W_ + u] = (r[0].x - lse) * LOG2E;

    if (u < U_) {
        const int tgt = target[b * U_ + u];
        float e = 0.f;
        bool have = false;
#pragma unroll
        for (int k = 0; k < 4; k++) {
            const int base = (k * 32 + lane) << 2;
            if (tgt >= base && tgt < base + 4) {
                have = true;
                if (tgt == base)     e = r[k].x;
                if (tgt == base + 1) e = r[k].y;
                if (tgt == base + 2) e = r[k].z;
                if (tgt == base + 3) e = r[k].w;
            }
        }
        if (have) g_dE[(b * D_ + d) * W_ + u + 1] = (e - lse) * LOG2E;
    }
}

// ---------------------------------------------------------------------------
// Kernel 2: single-warp wavefront DP, NO shared memory.
// Lane l owns u={2l,2l+1}; lane 31 also u=64. All step-n operands sit in
// row n-1 of the diagonal tables -> 4 coalesced LDG.64 per step, prefetched
// one 4-step group ahead (double-buffered registers).
// ---------------------------------------------------------------------------
__global__ void __launch_bounds__(32) dp_kernel(const int* __restrict__ pred_len,
                                                const int* __restrict__ target_len) {
    const int b = blockIdx.x;
    const int l = threadIdx.x;
    const int u0 = 2 * l;
    const int u1 = 2 * l + 1;

    const float2* B2 = (const float2*)(g_dB + b * D_ * W_);
    const float2* E2 = (const float2*)(g_dE + b * D_ * W_);

    const int plast = pred_len[b] - 1;
    const int tlen  = target_len[b];
    const float fblank = g_dB[(b * D_ + plast + tlen) * W_ + tlen];

    const int nh0 = plast + u0;
    const int nh1 = plast + u1;
    const int nh2 = plast + 64;

    float2 Bb[2][4], Ee[2][4], Xb[2][4], Xe[2][4];

#define LDGRP(G, N0)                                              \
    {  _Pragma("unroll")                                          \
       for (int k_ = 0; k_ < 4; k_++) {                           \
           const int r_ = min((N0) + k_ - 1, D_ - 1) * (W_ / 2);  \
           Bb[G][k_] = B2[r_ + l];                                \
           Ee[G][k_] = E2[r_ + l];                                \
           Xb[G][k_] = B2[r_ + 32];                               \
           Xe[G][k_] = E2[r_ + 32];                               \
       } }

    LDGRP(0, 1);

    float a0 = 0.f, a1 = 0.f, a2 = 0.f;          // lane0 a0 = alpha(0,0) = 0
    float res0 = 0.f, res1 = 0.f, res2 = 0.f;
    float left0 = 0.f;                            // dead for n=1 (emit sentinel)
    int cur = 0;

    for (int n0 = 1; n0 < D_; n0 += 4) {          // groups: 1-4, ..., 317-320
        LDGRP(cur ^ 1, n0 + 4);                   // clamped past end: harmless
#pragma unroll
        for (int k = 0; k < 4; k++) {
            const int n  = n0 + k;                // phantom n=320 fully masked
            const int t0 = n - u0;

            const float v0 = lae2(a0 + Bb[cur][k].x, left0 + Ee[cur][k].x);
            const float v1 = lae2(a1 + Bb[cur][k].y, a0 + Ee[cur][k].y);
            const float v2 = lae2(a2 + Xb[cur][k].x, a1 + Xe[cur][k].x);

            res0 = (n == nh0) ? v0 : res0;
            res1 = (n == nh1) ? v1 : res1;
            res2 = (n == nh2) ? v2 : res2;

            a0 = ((unsigned)t0       < (unsigned)T_) ? v0 : a0;
            a1 = ((unsigned)(t0 - 1) < (unsigned)T_) ? v1 : a1;
            a2 = ((unsigned)(n - 64) < (unsigned)T_) ? v2 : a2;

            left0 = __shfl_up_sync(0xffffffffu, a1, 1);
        }
        cur ^= 1;
    }
#undef LDGRP

    if (u0 == tlen)            g_partial[b] = -(res0 + fblank);
    if (u1 == tlen)            g_partial[b] = -(res1 + fblank);
    if (l == 31 && tlen == 64) g_partial[b] = -(res2 + fblank);
}

// ---------------------------------------------------------------------------
// Kernel 3: mean over batch (base-2 -> nat) -> d_out[0]
// ---------------------------------------------------------------------------
__global__ void finish_kernel(float* __restrict__ out) {
    if (threadIdx.x == 0) {
        float s = 0.f;
#pragma unroll
        for (int i = 0; i < B_; i++) s += g_partial[i];
        out[0] = s * (LN2 / B_);
    }
}

extern "C" void kernel_launch(void* const* d_in, const int* in_sizes, int n_in,
                              void* d_out, int out_size) {
    const float* pred       = (const float*)d_in[0];
    const int*   target     = (const int*)d_in[1];
    const int*   pred_len   = (const int*)d_in[2];
    const int*   target_len = (const int*)d_in[3];
    float*       out        = (float*)d_out;

    fill_kernel<<<(DIAG_ELEMS + 1023) / 1024, 1024>>>();
    lse_kernel<<<ROWS / 8, 256>>>(pred, target);
    dp_kernel<<<B_, 32>>>(pred_len, target_len);
    finish_kernel<<<1, 32>>>(out);
}

// round 11
// speedup vs baseline: 2.0736x; 1.2513x over previous
#include <cuda_runtime.h>
#include <math.h>

#define B_  8
#define T_  256
#define U_  64
#define U1_ 65
#define V_  512
#define D_  320                        // anti-diagonals t+u
#define DP_ 328                        // padded diagonal count (8 pad rows)
#define W_  66                         // padded diagonal width (33 float2)
#define SENT  -1e30f
#define LOG2E 1.4426950408889634f
#define LN2   0.6931471805599453f

#define ROWS (B_ * T_ * U1_)
#define DIAG_ELEMS (B_ * DP_ * W_)     // 173184

// Diagonal-major tables (base-2 log units), pre-filled with SENT:
//   g_dB[b][d][u]   = blank(t,u)*log2e at d=t+u   (invalid slots = SENT)
//   g_dE[b][d][u+1] = emit (t,u)*log2e at d=t+u   (col 0 & invalid = SENT)
__device__ float g_dB[DIAG_ELEMS];
__device__ float g_dE[DIAG_ELEMS];
__device__ float g_partial[B_];
__device__ unsigned g_count;

__device__ __forceinline__ float ex2(float x) {
    float y; asm("ex2.approx.f32 %0, %1;" : "=f"(y) : "f"(x)); return y;
}
__device__ __forceinline__ float lg2(float x) {
    float y; asm("lg2.approx.f32 %0, %1;" : "=f"(y) : "f"(x)); return y;
}
__device__ __forceinline__ float lae2(float a, float b) {
    const float mx = fmaxf(a, b);
    return mx + lg2(1.f + ex2(-fabsf(a - b)));
}

// ---------------------------------------------------------------------------
// Kernel 0: sentinel fill + ticket reset.
// ---------------------------------------------------------------------------
__global__ void fill_kernel() {
    const int i = blockIdx.x * 1024 + threadIdx.x;
    if (i < DIAG_ELEMS) { g_dB[i] = SENT; g_dE[i] = SENT; }
    if (i == 0) g_count = 0;
}

// ---------------------------------------------------------------------------
// Kernel 1: per-row log-softmax (HBM roofline); writes diagonal-major tables.
// ---------------------------------------------------------------------------
__global__ void __launch_bounds__(256) lse_kernel(const float* __restrict__ pred,
                                                  const int* __restrict__ target) {
    const int row  = blockIdx.x * 8 + (threadIdx.x >> 5);
    const int lane = threadIdx.x & 31;
    if (row >= ROWS) return;

    const float4* p = (const float4*)(pred + (size_t)row * V_);
    float4 r[4];
#pragma unroll
    for (int k = 0; k < 4; k++) r[k] = p[k * 32 + lane];

    float m = fmaxf(fmaxf(r[0].x, r[0].y), fmaxf(r[0].z, r[0].w));
#pragma unroll
    for (int k = 1; k < 4; k++)
        m = fmaxf(m, fmaxf(fmaxf(r[k].x, r[k].y), fmaxf(r[k].z, r[k].w)));
#pragma unroll
    for (int o = 16; o > 0; o >>= 1)
        m = fmaxf(m, __shfl_xor_sync(0xffffffffu, m, o));

    float s = 0.f;
#pragma unroll
    for (int k = 0; k < 4; k++)
        s += __expf(r[k].x - m) + __expf(r[k].y - m) +
             __expf(r[k].z - m) + __expf(r[k].w - m);
#pragma unroll
    for (int o = 16; o > 0; o >>= 1)
        s += __shfl_xor_sync(0xffffffffu, s, o);

    const float lse = m + __logf(s);

    const int u  = row % U1_;
    const int bt = row / U1_;
    const int t  = bt % T_;
    const int b  = bt / T_;
    const int d  = t + u;

    if (lane == 0)
        g_dB[(b * DP_ + d) * W_ + u] = (r[0].x - lse) * LOG2E;

    if (u < U_) {
        const int tgt = target[b * U_ + u];
        float e = 0.f;
        bool have = false;
#pragma unroll
        for (int k = 0; k < 4; k++) {
            const int base = (k * 32 + lane) << 2;
            if (tgt >= base && tgt < base + 4) {
                have = true;
                if (tgt == base)     e = r[k].x;
                if (tgt == base + 1) e = r[k].y;
                if (tgt == base + 2) e = r[k].z;
                if (tgt == base + 3) e = r[k].w;
            }
        }
        if (have) g_dE[(b * DP_ + d) * W_ + u + 1] = (e - lse) * LOG2E;
    }
}

// ---------------------------------------------------------------------------
// Kernel 2: single-warp wavefront DP (no SMEM) + fused final reduction.
// Lane l owns u={2l,2l+1}; lane 31 also u=64. 8-step groups, double-buffered
// register prefetch (issue-to-use >= ~8 steps). Alpha updates are UNGUARDED:
// sentinel algebra makes stale accumulators exactly self-correcting at t==0,
// and post-plast values are dead (res latched by its own selp).
// ---------------------------------------------------------------------------
__global__ void __launch_bounds__(32) dp_kernel(const int* __restrict__ pred_len,
                                                const int* __restrict__ target_len,
                                                float* __restrict__ out) {
    const int b = blockIdx.x;
    const int l = threadIdx.x;
    const int u0 = 2 * l;
    const int u1 = 2 * l + 1;

    const float2* B2 = (const float2*)(g_dB + b * DP_ * W_);
    const float2* E2 = (const float2*)(g_dE + b * DP_ * W_);

    const int plast = pred_len[b] - 1;
    const int tlen  = target_len[b];
    const float fblank = g_dB[(b * DP_ + plast + tlen) * W_ + tlen];

    const int nh0 = plast + u0;
    const int nh1 = plast + u1;
    const int nh2 = plast + 64;

    float2 Bb[2][8], Ee[2][8], Xb[2][8], Xe[2][8];

#define LDGRP(G, N0)                                              \
    {  _Pragma("unroll")                                          \
       for (int k_ = 0; k_ < 8; k_++) {                           \
           const int r_ = ((N0) + k_ - 1) * (W_ / 2);             \
           Bb[G][k_] = B2[r_ + l];                                \
           Ee[G][k_] = E2[r_ + l];                                \
           Xb[G][k_] = B2[r_ + 32];                               \
           Xe[G][k_] = E2[r_ + 32];                               \
       } }

    LDGRP(0, 1);

    float a0 = 0.f, a1 = 0.f, a2 = 0.f;          // lane0 a0 = alpha(0,0) = 0
    float res0 = 0.f, res1 = 0.f, res2 = 0.f;
    float left0 = 0.f;                            // dead for n=1 (emit sentinel)
    int cur = 0;

    for (int n0 = 1; n0 < D_ + 1; n0 += 8) {      // groups 1-8, ..., 313-320
        LDGRP(cur ^ 1, n0 + 8);                   // pad rows absorb overrun
#pragma unroll
        for (int k = 0; k < 8; k++) {
            const int n = n0 + k;                 // phantom n=320: res can't hit

            const float v0 = lae2(a0 + Bb[cur][k].x, left0 + Ee[cur][k].x);
            const float v1 = lae2(a1 + Bb[cur][k].y, a0 + Ee[cur][k].y);
            const float v2 = lae2(a2 + Xb[cur][k].x, a1 + Xe[cur][k].x);

            res0 = (n == nh0) ? v0 : res0;
            res1 = (n == nh1) ? v1 : res1;
            res2 = (n == nh2) ? v2 : res2;

            a0 = v0; a1 = v1; a2 = v2;            // unguarded (see header)

            left0 = __shfl_up_sync(0xffffffffu, a1, 1);
        }
        cur ^= 1;
    }
#undef LDGRP

    if (u0 == tlen)            g_partial[b] = -(res0 + fblank);
    if (u1 == tlen)            g_partial[b] = -(res1 + fblank);
    if (l == 31 && tlen == 64) g_partial[b] = -(res2 + fblank);

    // fused finish: last block to arrive sums in fixed order (deterministic)
    __syncwarp();
    __threadfence();
    if (l == 0) {
        const unsigned ticket = atomicAdd(&g_count, 1u);
        if (ticket == B_ - 1) {
            volatile float* gp = g_partial;
            float s = 0.f;
#pragma unroll
            for (int i = 0; i < B_; i++) s += gp[i];
            out[0] = s * (LN2 / B_);
        }
    }
}

extern "C" void kernel_launch(void* const* d_in, const int* in_sizes, int n_in,
                              void* d_out, int out_size) {
    const float* pred       = (const float*)d_in[0];
    const int*   target     = (const int*)d_in[1];
    const int*   pred_len   = (const int*)d_in[2];
    const int*   target_len = (const int*)d_in[3];
    float*       out        = (float*)d_out;

    fill_kernel<<<(DIAG_ELEMS + 1023) / 1024, 1024>>>();
    lse_kernel<<<ROWS / 8, 256>>>(pred, target);
    dp_kernel<<<B_, 32>>>(pred_len, target_len, out);
}

// round 12
// speedup vs baseline: 2.1252x; 1.0249x over previous
#include <cuda_runtime.h>
#include <math.h>

#define B_  8
#define T_  256
#define U_  64
#define U1_ 65
#define V_  512
#define D_  320                        // anti-diagonals t+u
#define DP_ 328                        // padded diagonal count
#define SENT  -1e30f
#define LOG2E 1.4426950408889634f
#define LN2   0.6931471805599453f

#define ROWS (B_ * T_ * U1_)
#define F_ELEMS (B_ * DP_ * 32)        // float4 count = 83968
#define X_ELEMS (B_ * DP_)             // float2 count = 2624

// Merged diagonal-major tables (base-2 log units), SENT-prefilled.
// F[b][r][l] = (blank(r-2l,2l), blank(r-2l-1,2l+1), emit(r-2l,2l-1), emit(r-2l-1,2l))
// X[b][r]    = (blank(r-64,64), emit(r-63,63))
__device__ float4 g_dF[F_ELEMS];
__device__ float2 g_dX[X_ELEMS];
__device__ float  g_partial[B_];
__device__ unsigned g_count;

__device__ __forceinline__ float ex2(float x) {
    float y; asm("ex2.approx.f32 %0, %1;" : "=f"(y) : "f"(x)); return y;
}
__device__ __forceinline__ float lg2(float x) {
    float y; asm("lg2.approx.f32 %0, %1;" : "=f"(y) : "f"(x)); return y;
}
__device__ __forceinline__ float lae2(float a, float b) {
    const float mx = fmaxf(a, b);
    return mx + lg2(1.f + ex2(-fabsf(a - b)));
}

// ---------------------------------------------------------------------------
// Kernel 0: sentinel fill + ticket reset.
// ---------------------------------------------------------------------------
__global__ void fill_kernel() {
    const int i = blockIdx.x * 1024 + threadIdx.x;
    if (i < F_ELEMS) g_dF[i] = make_float4(SENT, SENT, SENT, SENT);
    if (i < X_ELEMS) g_dX[i] = make_float2(SENT, SENT);
    if (i == 0) g_count = 0;
}

// ---------------------------------------------------------------------------
// Kernel 1: per-row log-softmax (HBM roofline); writes merged diag tables.
// ---------------------------------------------------------------------------
__global__ void __launch_bounds__(256) lse_kernel(const float* __restrict__ pred,
                                                  const int* __restrict__ target) {
    const int row  = blockIdx.x * 8 + (threadIdx.x >> 5);
    const int lane = threadIdx.x & 31;
    if (row >= ROWS) return;

    const float4* p = (const float4*)(pred + (size_t)row * V_);
    float4 r[4];
#pragma unroll
    for (int k = 0; k < 4; k++) r[k] = p[k * 32 + lane];

    float m = fmaxf(fmaxf(r[0].x, r[0].y), fmaxf(r[0].z, r[0].w));
#pragma unroll
    for (int k = 1; k < 4; k++)
        m = fmaxf(m, fmaxf(fmaxf(r[k].x, r[k].y), fmaxf(r[k].z, r[k].w)));
#pragma unroll
    for (int o = 16; o > 0; o >>= 1)
        m = fmaxf(m, __shfl_xor_sync(0xffffffffu, m, o));

    float s = 0.f;
#pragma unroll
    for (int k = 0; k < 4; k++)
        s += __expf(r[k].x - m) + __expf(r[k].y - m) +
             __expf(r[k].z - m) + __expf(r[k].w - m);
#pragma unroll
    for (int o = 16; o > 0; o >>= 1)
        s += __shfl_xor_sync(0xffffffffu, s, o);

    const float lse = m + __logf(s);

    const int u  = row % U1_;
    const int bt = row / U1_;
    const int t  = bt % T_;
    const int b  = bt / T_;

    float* Ff = (float*)g_dF;

    if (lane == 0) {
        const float bl = (r[0].x - lse) * LOG2E;
        if (u == 64) {
            g_dX[b * DP_ + t + 64].x = bl;
        } else {
            // u even -> .x (comp 0); u odd -> .y (comp 1); pair l = u>>1; row t+u
            const int l = u >> 1;
            Ff[(((b * DP_ + t + u) * 32) + l) * 4 + (u & 1)] = bl;
        }
    }

    if (u < U_) {
        const int tgt = target[b * U_ + u];
        float e = 0.f;
        bool have = false;
#pragma unroll
        for (int k = 0; k < 4; k++) {
            const int base = (k * 32 + lane) << 2;
            if (tgt >= base && tgt < base + 4) {
                have = true;
                if (tgt == base)     e = r[k].x;
                if (tgt == base + 1) e = r[k].y;
                if (tgt == base + 2) e = r[k].z;
                if (tgt == base + 3) e = r[k].w;
            }
        }
        if (have) {
            const float em = (e - lse) * LOG2E;
            if (u == 63) {
                g_dX[b * DP_ + t + 63].y = em;
            } else if (u & 1) {
                // emA: pair (u+1)/2, comp .z (2); row t+u+1
                Ff[(((b * DP_ + t + u + 1) * 32) + ((u + 1) >> 1)) * 4 + 2] = em;
            } else {
                // emB: pair u/2, comp .w (3); row t+u+1
                Ff[(((b * DP_ + t + u + 1) * 32) + (u >> 1)) * 4 + 3] = em;
            }
        }
    }
}

// ---------------------------------------------------------------------------
// Kernel 2: single-warp wavefront DP + fused final reduction.
// Lane l owns u={2l,2l+1}; lane 31 also u=64. One LDG.128 + one LDG.64 per
// step (double-buffered 8-step groups). Unguarded alpha chain (sentinel
// algebra self-corrects at t==0; post-plast values dead).
// ---------------------------------------------------------------------------
__global__ void __launch_bounds__(32) dp_kernel(const int* __restrict__ pred_len,
                                                const int* __restrict__ target_len,
                                                float* __restrict__ out) {
    const int b = blockIdx.x;
    const int l = threadIdx.x;
    const int u0 = 2 * l;
    const int u1 = 2 * l + 1;

    const float4* F4 = g_dF + b * DP_ * 32;
    const float2* X2 = g_dX + b * DP_;

    const int plast = pred_len[b] - 1;
    const int tlen  = target_len[b];

    // blank(plast, tlen) from merged tables
    float fblank;
    if (tlen == 64)
        fblank = X2[plast + 64].x;
    else
        fblank = ((const float*)F4)[(((plast + tlen) * 32) + (tlen >> 1)) * 4 + (tlen & 1)];

    const int nh0 = plast + u0;
    const int nh1 = plast + u1;
    const int nh2 = plast + 64;

    float4 Fb[2][8];
    float2 Xb[2][8];

#define LDGRP(G, N0)                                              \
    {  _Pragma("unroll")                                          \
       for (int k_ = 0; k_ < 8; k_++) {                           \
           const int r_ = (N0) + k_ - 1;                          \
           Fb[G][k_] = F4[r_ * 32 + l];                           \
           Xb[G][k_] = X2[r_];                                    \
       } }

    LDGRP(0, 1);

    float a0 = 0.f, a1 = 0.f, a2 = 0.f;          // lane0 a0 = alpha(0,0) = 0
    float res0 = 0.f, res1 = 0.f, res2 = 0.f;
    float left0 = 0.f;                            // dead for n=1 (emit sentinel)
    int cur = 0;

    for (int n0 = 1; n0 < D_ + 1; n0 += 8) {      // groups 1-8, ..., 313-320
        LDGRP(cur ^ 1, n0 + 8);                   // pad rows absorb overrun
#pragma unroll
        for (int k = 0; k < 8; k++) {
            const int n = n0 + k;                 // phantom n=320: res can't hit
            const float4 f = Fb[cur][k];
            const float2 x = Xb[cur][k];

            const float v0 = lae2(a0 + f.x, left0 + f.z);
            const float v1 = lae2(a1 + f.y, a0 + f.w);
            const float v2 = lae2(a2 + x.x, a1 + x.y);

            res0 = (n == nh0) ? v0 : res0;
            res1 = (n == nh1) ? v1 : res1;
            res2 = (n == nh2) ? v2 : res2;

            a0 = v0; a1 = v1; a2 = v2;            // unguarded (see header)

            left0 = __shfl_up_sync(0xffffffffu, a1, 1);
        }
        cur ^= 1;
    }
#undef LDGRP

    if (u0 == tlen)            g_partial[b] = -(res0 + fblank);
    if (u1 == tlen)            g_partial[b] = -(res1 + fblank);
    if (l == 31 && tlen == 64) g_partial[b] = -(res2 + fblank);

    // fused finish: last block to arrive sums in fixed order (deterministic)
    __syncwarp();
    __threadfence();
    if (l == 0) {
        const unsigned ticket = atomicAdd(&g_count, 1u);
        if (ticket == B_ - 1) {
            volatile float* gp = g_partial;
            float s = 0.f;
#pragma unroll
            for (int i = 0; i < B_; i++) s += gp[i];
            out[0] = s * (LN2 / B_);
        }
    }
}

extern "C" void kernel_launch(void* const* d_in, const int* in_sizes, int n_in,
                              void* d_out, int out_size) {
    const float* pred       = (const float*)d_in[0];
    const int*   target     = (const int*)d_in[1];
    const int*   pred_len   = (const int*)d_in[2];
    const int*   target_len = (const int*)d_in[3];
    float*       out        = (float*)d_out;

    fill_kernel<<<(F_ELEMS + 1023) / 1024, 1024>>>();
    lse_kernel<<<ROWS / 8, 256>>>(pred, target);
    dp_kernel<<<B_, 32>>>(pred_len, target_len, out);
}

// round 15
// speedup vs baseline: 2.2322x; 1.0504x over previous
#include <cuda_runtime.h>
#include <math.h>

#define B_  8
#define T_  256
#define U_  64
#define U1_ 65
#define V_  512
#define D_  320                        // anti-diagonals t+u
#define DP_ 328                        // padded diagonal count
#define SENT  -1e30f
#define LOG2E 1.4426950408889634f
#define LN2   0.6931471805599453f

#define ROWS (B_ * T_ * U1_)
#define LSE_BLOCKS (ROWS / 8)          // 16640
#define F_ELEMS (B_ * DP_ * 32)        // 83968 float4 slots
#define Z_ELEMS (B_ * DP_)             // 2624
#define FILL_BLOCKS ((F_ELEMS + 255) / 256)   // 328

// Merged diagonal-major table (base-2 log units). Slot (b, r, l):
//   .x = blank(r-2l-1, 2l+1)   .y = blank(r-2l-2, 2l+2)
//   .z = emit (r-2l,   2l  )   .w = emit (r-2l-1, 2l+1)
// i.e. every entry for cell value (t,u) sits at row t+u. Never-valid slots
// hold SENT (written by the fused fill part, address-disjoint from lse).
// g_dZ[b][t] = blank(t, 0) (u=0 column chain); rows t>=T_ = SENT.
__device__ float4 g_dG[F_ELEMS];
__device__ float  g_dZ[Z_ELEMS];
__device__ float  g_partial[B_];
__device__ unsigned g_count;

__device__ __forceinline__ float ex2(float x) {
    float y; asm("ex2.approx.f32 %0, %1;" : "=f"(y) : "f"(x)); return y;
}
__device__ __forceinline__ float lg2(float x) {
    float y; asm("lg2.approx.f32 %0, %1;" : "=f"(y) : "f"(x)); return y;
}
__device__ __forceinline__ float lae2(float a, float b) {
    const float mx = fmaxf(a, b);
    return mx + lg2(1.f + ex2(-fabsf(a - b)));
}

// ---------------------------------------------------------------------------
// Kernel 1: fused [log-softmax writer | sentinel fill]. The fill part writes
// SENT only to slots no lse warp ever writes -> no ordering required.
// ---------------------------------------------------------------------------
__global__ void __launch_bounds__(256) lse_kernel(const float* __restrict__ pred,
                                                  const int* __restrict__ target) {
    if (blockIdx.x >= LSE_BLOCKS) {
        // ---- sentinel fill part ----
        const int gidx = (blockIdx.x - LSE_BLOCKS) * 256 + threadIdx.x;
        if (gidx == 0) g_count = 0;
        if (gidx < Z_ELEMS && (gidx % DP_) >= T_) g_dZ[gidx] = SENT;
        if (gidx < F_ELEMS) {
            const int l = gidx & 31;
            const int r = (gidx >> 5) % DP_;
            float* fp = (float*)(g_dG + gidx);
            const int txw = r - 2 * l - 1;             // .x and .w share validity
            const int ty  = r - 2 * l - 2;
            const int tz  = r - 2 * l;
            if ((unsigned)txw >= (unsigned)T_) { fp[0] = SENT; fp[3] = SENT; }
            if ((unsigned)ty  >= (unsigned)T_)   fp[1] = SENT;
            if ((unsigned)tz  >= (unsigned)T_)   fp[2] = SENT;
        }
        return;
    }

    const int row  = blockIdx.x * 8 + (threadIdx.x >> 5);
    const int lane = threadIdx.x & 31;

    const float4* p = (const float4*)(pred + (size_t)row * V_);
    float4 r[4];
#pragma unroll
    for (int k = 0; k < 4; k++) r[k] = p[k * 32 + lane];

    float m = fmaxf(fmaxf(r[0].x, r[0].y), fmaxf(r[0].z, r[0].w));
#pragma unroll
    for (int k = 1; k < 4; k++)
        m = fmaxf(m, fmaxf(fmaxf(r[k].x, r[k].y), fmaxf(r[k].z, r[k].w)));
#pragma unroll
    for (int o = 16; o > 0; o >>= 1)
        m = fmaxf(m, __shfl_xor_sync(0xffffffffu, m, o));

    float s = 0.f;
#pragma unroll
    for (int k = 0; k < 4; k++)
        s += __expf(r[k].x - m) + __expf(r[k].y - m) +
             __expf(r[k].z - m) + __expf(r[k].w - m);
#pragma unroll
    for (int o = 16; o > 0; o >>= 1)
        s += __shfl_xor_sync(0xffffffffu, s, o);

    const float lse = m + __logf(s);

    const int u  = row % U1_;
    const int bt = row / U1_;
    const int t  = bt % T_;
    const int b  = bt / T_;

    float* Gf = (float*)g_dG;

    if (lane == 0) {
        const float bl = (r[0].x - lse) * LOG2E;
        if (u == 0)
            g_dZ[b * DP_ + t] = bl;
        else if (u & 1)   // odd u -> .x, pair (u-1)/2, row t+u
            Gf[(((b * DP_ + t + u) * 32) + ((u - 1) >> 1)) * 4 + 0] = bl;
        else              // even u>=2 -> .y, pair (u-2)/2, row t+u
            Gf[(((b * DP_ + t + u) * 32) + ((u - 2) >> 1)) * 4 + 1] = bl;
    }

    if (u < U_) {
        const int tgt = target[b * U_ + u];
        float e = 0.f;
        bool have = false;
#pragma unroll
        for (int k = 0; k < 4; k++) {
            const int base = (k * 32 + lane) << 2;
            if (tgt >= base && tgt < base + 4) {
                have = true;
                if (tgt == base)     e = r[k].x;
                if (tgt == base + 1) e = r[k].y;
                if (tgt == base + 2) e = r[k].z;
                if (tgt == base + 3) e = r[k].w;
            }
        }
        if (have) {
            const float em = (e - lse) * LOG2E;
            if (u & 1)    // odd u -> .w, pair (u-1)/2, row t+u
                Gf[(((b * DP_ + t + u) * 32) + ((u - 1) >> 1)) * 4 + 3] = em;
            else          // even u -> .z, pair u/2, row t+u
                Gf[(((b * DP_ + t + u) * 32) + (u >> 1)) * 4 + 2] = em;
        }
    }
}

// ---------------------------------------------------------------------------
// Kernel 2: single-warp wavefront DP + fused final reduction.
// Lane l owns u={2l+1, 2l+2}; lane 0 also carries the u=0 column as a pure
// add chain z (no lae2). 2 lae2/step (4 MUFU). One LDG.128 + one uniform
// LDG.32 per step, double-buffered 8-step groups. Unguarded alpha chain:
// sentinels self-correct at each cell's first valid step; post-capture
// values are dead (res latched by its own selp).
// ---------------------------------------------------------------------------
__global__ void __launch_bounds__(32) dp_kernel(const int* __restrict__ pred_len,
                                                const int* __restrict__ target_len,
                                                float* __restrict__ out) {
    const int b = blockIdx.x;
    const int l = threadIdx.x;
    const int ua = 2 * l + 1;
    const int ub = 2 * l + 2;

    const float4* G4 = g_dG + b * DP_ * 32;
    const float*  Zp = g_dZ + b * DP_;

    const int plast = pred_len[b] - 1;
    const int tlen  = target_len[b];          // in [56, 64] -> never 0

    const float fblank = (tlen & 1)
        ? ((const float*)G4)[(((plast + tlen) * 32) + ((tlen - 1) >> 1)) * 4 + 0]
        : ((const float*)G4)[(((plast + tlen) * 32) + ((tlen - 2) >> 1)) * 4 + 1];

    const int nha = plast + ua;
    const int nhb = plast + ub;

    float4 Gb[2][8];
    float  Zb[2][8];

#define LDGRP(G, N0)                                              \
    {  _Pragma("unroll")                                          \
       for (int k_ = 0; k_ < 8; k_++) {                           \
           const int r_ = (N0) + k_ - 1;                          \
           Gb[G][k_] = G4[r_ * 32 + l];                           \
           Zb[G][k_] = Zp[r_];                                    \
       } }

    LDGRP(0, 1);

    float aa = 0.f, ab = 0.f;                 // dead until sentinel-corrected
    float z = 0.f;                            // alpha(0,0) = 0
    float left = 0.f;                         // lane0: alpha(0,0); others dead
    float resa = 0.f, resb = 0.f;
    int cur = 0;

    for (int n0 = 1; n0 < D_ + 1; n0 += 8) {  // groups 1-8, ..., 313-320
        LDGRP(cur ^ 1, n0 + 8);               // pad rows absorb overrun
#pragma unroll
        for (int k = 0; k < 8; k++) {
            const int n = n0 + k;             // phantom n=320: res can't hit
            const float4 f = Gb[cur][k];

            const float va = lae2(aa + f.x, left + f.z);
            const float vb = lae2(ab + f.y, aa + f.w);
            z += Zb[cur][k];                  // alpha(n, 0)

            resa = (n == nha) ? va : resa;
            resb = (n == nhb) ? vb : resb;

            aa = va; ab = vb;                 // unguarded (see header)

            const float sh = __shfl_up_sync(0xffffffffu, ab, 1);
            left = (l == 0) ? z : sh;         // alpha(t_a, u_a-1) for step n+1
        }
        cur ^= 1;
    }
#undef LDGRP

    if (ua == tlen) g_partial[b] = -(resa + fblank);
    if (ub == tlen) g_partial[b] = -(resb + fblank);

    // fused finish: last block to arrive sums in fixed order (deterministic)
    __syncwarp();
    __threadfence();
    if (l == 0) {
        const unsigned ticket = atomicAdd(&g_count, 1u);
        if (ticket == B_ - 1) {
            volatile float* gp = g_partial;
            float s = 0.f;
#pragma unroll
            for (int i = 0; i < B_; i++) s += gp[i];
            out[0] = s * (LN2 / B_);
        }
    }
}

extern "C" void kernel_launch(void* const* d_in, const int* in_sizes, int n_in,
                              void* d_out, int out_size) {
    const float* pred       = (const float*)d_in[0];
    const int*   target     = (const int*)d_in[1];
    const int*   pred_len   = (const int*)d_in[2];
    const int*   target_len = (const int*)d_in[3];
    float*       out        = (float*)d_out;

    lse_kernel<<<LSE_BLOCKS + FILL_BLOCKS, 256>>>(pred, target);
    dp_kernel<<<B_, 32>>>(pred_len, target_len, out);
}

// round 16
// speedup vs baseline: 2.6452x; 1.1850x over previous
#include <cuda_runtime.h>
#include <math.h>

#define B_  8
#define T_  256
#define U_  64
#define U1_ 65
#define V_  512
#define D_  320                        // anti-diagonals t+u
#define DP_ 328                        // padded diagonal count
#define SENT  -1e30f
#define LOG2E 1.4426950408889634f
#define LN2   0.6931471805599453f

#define ROWS (B_ * T_ * U1_)
#define LSE_BLOCKS (ROWS / 8)          // 16640
#define F_ELEMS (B_ * DP_ * 32)        // 83968 float4 slots
#define Z_ELEMS (B_ * DP_)             // 2624
#define FILL_BLOCKS ((F_ELEMS + 255) / 256)   // 328
#define RING 4                         // smem ring: 4 groups x 8 rows

// Merged diagonal-major table (base-2 log units). Slot (b, r, l):
//   .x = blank(r-2l-1, 2l+1)   .y = blank(r-2l-2, 2l+2)
//   .z = emit (r-2l,   2l  )   .w = emit (r-2l-1, 2l+1)
// Every entry for cell (t,u) sits at row t+u; never-valid slots = SENT.
// g_dZ[b][t] = blank(t, 0); rows t>=T_ = SENT.
__device__ float4 g_dG[F_ELEMS];
__device__ float  g_dZ[Z_ELEMS];
__device__ float  g_partial[B_];
__device__ unsigned g_count;

__device__ __forceinline__ float ex2(float x) {
    float y; asm("ex2.approx.f32 %0, %1;" : "=f"(y) : "f"(x)); return y;
}
__device__ __forceinline__ float lg2(float x) {
    float y; asm("lg2.approx.f32 %0, %1;" : "=f"(y) : "f"(x)); return y;
}
__device__ __forceinline__ float lae2(float a, float b) {
    const float mx = fmaxf(a, b);
    return mx + lg2(1.f + ex2(-fabsf(a - b)));
}

// ---------------------------------------------------------------------------
// Kernel 1: fused [log-softmax writer | sentinel fill] (address-disjoint).
// ---------------------------------------------------------------------------
__global__ void __launch_bounds__(256) lse_kernel(const float* __restrict__ pred,
                                                  const int* __restrict__ target) {
    if (blockIdx.x >= LSE_BLOCKS) {
        const int gidx = (blockIdx.x - LSE_BLOCKS) * 256 + threadIdx.x;
        if (gidx == 0) g_count = 0;
        if (gidx < Z_ELEMS && (gidx % DP_) >= T_) g_dZ[gidx] = SENT;
        if (gidx < F_ELEMS) {
            const int l = gidx & 31;
            const int r = (gidx >> 5) % DP_;
            float* fp = (float*)(g_dG + gidx);
            const int txw = r - 2 * l - 1;
            const int ty  = r - 2 * l - 2;
            const int tz  = r - 2 * l;
            if ((unsigned)txw >= (unsigned)T_) { fp[0] = SENT; fp[3] = SENT; }
            if ((unsigned)ty  >= (unsigned)T_)   fp[1] = SENT;
            if ((unsigned)tz  >= (unsigned)T_)   fp[2] = SENT;
        }
        return;
    }

    const int row  = blockIdx.x * 8 + (threadIdx.x >> 5);
    const int lane = threadIdx.x & 31;

    const float4* p = (const float4*)(pred + (size_t)row * V_);
    float4 r[4];
#pragma unroll
    for (int k = 0; k < 4; k++) r[k] = p[k * 32 + lane];

    float m = fmaxf(fmaxf(r[0].x, r[0].y), fmaxf(r[0].z, r[0].w));
#pragma unroll
    for (int k = 1; k < 4; k++)
        m = fmaxf(m, fmaxf(fmaxf(r[k].x, r[k].y), fmaxf(r[k].z, r[k].w)));
#pragma unroll
    for (int o = 16; o > 0; o >>= 1)
        m = fmaxf(m, __shfl_xor_sync(0xffffffffu, m, o));

    float s = 0.f;
#pragma unroll
    for (int k = 0; k < 4; k++)
        s += __expf(r[k].x - m) + __expf(r[k].y - m) +
             __expf(r[k].z - m) + __expf(r[k].w - m);
#pragma unroll
    for (int o = 16; o > 0; o >>= 1)
        s += __shfl_xor_sync(0xffffffffu, s, o);

    const float lse = m + __logf(s);

    const int u  = row % U1_;
    const int bt = row / U1_;
    const int t  = bt % T_;
    const int b  = bt / T_;

    float* Gf = (float*)g_dG;

    if (lane == 0) {
        const float bl = (r[0].x - lse) * LOG2E;
        if (u == 0)
            g_dZ[b * DP_ + t] = bl;
        else if (u & 1)   // odd u -> .x, pair (u-1)/2, row t+u
            Gf[(((b * DP_ + t + u) * 32) + ((u - 1) >> 1)) * 4 + 0] = bl;
        else              // even u>=2 -> .y, pair (u-2)/2, row t+u
            Gf[(((b * DP_ + t + u) * 32) + ((u - 2) >> 1)) * 4 + 1] = bl;
    }

    if (u < U_) {
        const int tgt = target[b * U_ + u];
        float e = 0.f;
        bool have = false;
#pragma unroll
        for (int k = 0; k < 4; k++) {
            const int base = (k * 32 + lane) << 2;
            if (tgt >= base && tgt < base + 4) {
                have = true;
                if (tgt == base)     e = r[k].x;
                if (tgt == base + 1) e = r[k].y;
                if (tgt == base + 2) e = r[k].z;
                if (tgt == base + 3) e = r[k].w;
            }
        }
        if (have) {
            const float em = (e - lse) * LOG2E;
            if (u & 1)    // odd u -> .w, pair (u-1)/2, row t+u
                Gf[(((b * DP_ + t + u) * 32) + ((u - 1) >> 1)) * 4 + 3] = em;
            else          // even u -> .z, pair u/2, row t+u
                Gf[(((b * DP_ + t + u) * 32) + (u >> 1)) * 4 + 2] = em;
        }
    }
}

// ---------------------------------------------------------------------------
// Kernel 2: single-warp wavefront DP + fused final reduction.
// cp.async ring (4 groups x 8 rows, static SMEM) prefetches 3 groups (~24
// steps) ahead with ZERO register cost -> L2 latency fully covered (the
// R15 regs=64 ceiling proved register prefetch never materialized).
// Lane l owns u={2l+1, 2l+2}; lane 0 carries u=0 column as add chain.
// Each lane reads only the smem column it wrote (per-thread cp.async order).
// ---------------------------------------------------------------------------
__global__ void __launch_bounds__(32) dp_kernel(const int* __restrict__ pred_len,
                                                const int* __restrict__ target_len,
                                                float* __restrict__ out) {
    __shared__ float4 sG[RING][8][32];
    __shared__ float  sZ[DP_];

    const int b = blockIdx.x;
    const int l = threadIdx.x;
    const int ua = 2 * l + 1;
    const int ub = 2 * l + 2;

    const float4* G4 = g_dG + b * DP_ * 32;
    const float*  Zp = g_dZ + b * DP_;

    // preload full Z column (u=0 chain operands)
    for (int i = l; i < DP_; i += 32) sZ[i] = Zp[i];
    __syncwarp();

#define ISSUE_GROUP(g)                                                      \
    { const int g_ = (g);                                                   \
      const float4* src_ = G4 + g_ * 8 * 32 + l;                            \
      float4* dst_ = &sG[g_ & (RING - 1)][0][l];                            \
      _Pragma("unroll")                                                     \
      for (int k_ = 0; k_ < 8; k_++) {                                      \
          unsigned da_ = (unsigned)__cvta_generic_to_shared(dst_ + k_ * 32);\
          asm volatile("cp.async.cg.shared.global [%0], [%1], 16;"          \
                       :: "r"(da_), "l"(src_ + k_ * 32));                   \
      } }
#define COMMIT()  asm volatile("cp.async.commit_group;")
#define WAIT3()   asm volatile("cp.async.wait_group 3;")

    ISSUE_GROUP(0); COMMIT();
    ISSUE_GROUP(1); COMMIT();
    ISSUE_GROUP(2); COMMIT();

    const int plast = pred_len[b] - 1;
    const int tlen  = target_len[b];          // in [56,64] -> never 0

    const float fblank = (tlen & 1)
        ? ((const float*)G4)[(((plast + tlen) * 32) + ((tlen - 1) >> 1)) * 4 + 0]
        : ((const float*)G4)[(((plast + tlen) * 32) + ((tlen - 2) >> 1)) * 4 + 1];

    const int nha = plast + ua;
    const int nhb = plast + ub;

    float aa = 0.f, ab = 0.f;                 // dead until sentinel-corrected
    float z = 0.f;                            // alpha(0,0) = 0
    float left = 0.f;                         // lane0: alpha(0,0); others dead
    float resa = 0.f, resb = 0.f;

    for (int g = 0; g < 40; g++) {            // group g covers steps 8g+1..8g+8
        if (g + 3 < 40) { ISSUE_GROUP(g + 3); }
        COMMIT();                             // always commit (maybe empty)
        WAIT3();                              // group g's data resident
        const int slot = g & (RING - 1);
        const int n0 = 8 * g + 1;
#pragma unroll
        for (int k = 0; k < 8; k++) {
            const int n = n0 + k;             // phantom n=320: res can't hit
            const float4 f = sG[slot][k][l];

            const float va = lae2(aa + f.x, left + f.z);
            const float vb = lae2(ab + f.y, aa + f.w);
            z += sZ[n - 1];                   // alpha(n, 0)

            resa = (n == nha) ? va : resa;
            resb = (n == nhb) ? vb : resb;

            aa = va; ab = vb;                 // unguarded (sentinel algebra)

            const float sh = __shfl_up_sync(0xffffffffu, ab, 1);
            left = (l == 0) ? z : sh;         // alpha(., u_a - 1) for step n+1
        }
    }
#undef ISSUE_GROUP
#undef COMMIT
#undef WAIT3

    if (ua == tlen) g_partial[b] = -(resa + fblank);
    if (ub == tlen) g_partial[b] = -(resb + fblank);

    // fused finish: last block sums in fixed order (deterministic)
    __syncwarp();
    __threadfence();
    if (l == 0) {
        const unsigned ticket = atomicAdd(&g_count, 1u);
        if (ticket == B_ - 1) {
            volatile float* gp = g_partial;
            float s = 0.f;
#pragma unroll
            for (int i = 0; i < B_; i++) s += gp[i];
            out[0] = s * (LN2 / B_);
        }
    }
}

extern "C" void kernel_launch(void* const* d_in, const int* in_sizes, int n_in,
                              void* d_out, int out_size) {
    const float* pred       = (const float*)d_in[0];
    const int*   target     = (const int*)d_in[1];
    const int*   pred_len   = (const int*)d_in[2];
    const int*   target_len = (const int*)d_in[3];
    float*       out        = (float*)d_out;

    lse_kernel<<<LSE_BLOCKS + FILL_BLOCKS, 256>>>(pred, target);
    dp_kernel<<<B_, 32>>>(pred_len, target_len, out);
}